// round 1
// baseline (speedup 1.0000x reference)
#include <cuda_runtime.h>
#include <math.h>

// Problem dims (fixed by the dataset)
#define TT 8192
#define DD 1024
#define HH 4096
#define EE 8

// GEMM tiling
#define BM 128
#define BN 128
#define BK 16
#define TM 8
#define TN 8

// ---------------- scratch (static device globals; no allocations) ----------
__device__ int   g_count[EE];
__device__ int   g_cursor[EE];
__device__ int   g_offset[EE];
__device__ int   g_sel[TT * 2];
__device__ float g_wt[TT * 2];
__device__ int   g_btok[TT * 2];               // bucket: token ids grouped by expert
__device__ float g_bw[TT * 2];                 // bucket: renormalized gate weights
__device__ int   g_pos[TT * 2];                // (token,slot) -> bucket index
__device__ float g_h[(size_t)TT * 2 * HH];     // grouped gated activations  (268 MB)
__device__ float g_yb[(size_t)TT * 2 * DD];    // grouped partial outputs    (67 MB)

// ---------------- kernels ---------------------------------------------------

__global__ void k_zero() {
    if (threadIdx.x < EE) g_count[threadIdx.x] = 0;
}

// Router: logits = x @ Wg^T, softmax, top-2, renormalize. One warp per token.
__global__ void k_router(const float* __restrict__ x, const float* __restrict__ Wg,
                         float* __restrict__ out_logits) {
    int t = blockIdx.x * (blockDim.x >> 5) + (threadIdx.x >> 5);
    int lane = threadIdx.x & 31;
    if (t >= TT) return;
    const float* xr = x + (size_t)t * DD;

    float acc[EE];
#pragma unroll
    for (int e = 0; e < EE; e++) acc[e] = 0.f;
    for (int j = lane; j < DD; j += 32) {
        float xv = xr[j];
#pragma unroll
        for (int e = 0; e < EE; e++) acc[e] = fmaf(xv, Wg[e * DD + j], acc[e]);
    }
#pragma unroll
    for (int e = 0; e < EE; e++) {
#pragma unroll
        for (int o = 16; o > 0; o >>= 1) acc[e] += __shfl_xor_sync(0xffffffffu, acc[e], o);
    }
    if (lane == 0) {
        float mx = acc[0];
#pragma unroll
        for (int e = 1; e < EE; e++) mx = fmaxf(mx, acc[e]);
        float p[EE];
        float den = 0.f;
#pragma unroll
        for (int e = 0; e < EE; e++) { p[e] = expf(acc[e] - mx); den += p[e]; }
        float inv = 1.f / den;
#pragma unroll
        for (int e = 0; e < EE; e++) p[e] *= inv;

        // top-2 (strict > keeps lowest index on ties, matching lax.top_k)
        int i0 = 0;
#pragma unroll
        for (int e = 1; e < EE; e++) if (p[e] > p[i0]) i0 = e;
        int i1 = (i0 == 0) ? 1 : 0;
#pragma unroll
        for (int e = 0; e < EE; e++) if (e != i0 && p[e] > p[i1]) i1 = e;

        float w0 = p[i0], w1 = p[i1];
        float s = 1.f / (w0 + w1);
        w0 *= s; w1 *= s;

        g_sel[t * 2] = i0; g_sel[t * 2 + 1] = i1;
        g_wt[t * 2] = w0;  g_wt[t * 2 + 1] = w1;
        atomicAdd(&g_count[i0], 1);
        atomicAdd(&g_count[i1], 1);
#pragma unroll
        for (int e = 0; e < EE; e++) out_logits[(size_t)t * EE + e] = acc[e];
    }
}

__global__ void k_offsets() {
    int o = 0;
    for (int e = 0; e < EE; e++) { g_offset[e] = o; g_cursor[e] = o; o += g_count[e]; }
}

__global__ void k_scatter() {
    int t = blockIdx.x * blockDim.x + threadIdx.x;
    if (t >= TT) return;
#pragma unroll
    for (int k = 0; k < 2; k++) {
        int e = g_sel[t * 2 + k];
        int idx = atomicAdd(&g_cursor[e], 1);
        g_btok[idx] = t;
        g_bw[idx] = g_wt[t * 2 + k];
        g_pos[t * 2 + k] = idx;
    }
}

// Grouped GEMM. UP=true:  C=g_h[idx] = gelu(x[gather] @ W1[e]) * gate
//              UP=false: C=g_yb[idx] = g_h[idx] @ W2[e]
template<int KD, int ND, bool UP>
__global__ __launch_bounds__(256, 2)
void k_ggemm(const float* __restrict__ Ag, const float* __restrict__ Bg) {
    const int e = blockIdx.z;
    const int cnt = g_count[e];
    const int rt = blockIdx.y;
    if (rt * BM >= cnt) return;
    const int off = g_offset[e];
    const int n0 = blockIdx.x * BN;
    const int tid = threadIdx.x;

    __shared__ float As[2][BK][BM + 4];
    __shared__ float Bs[2][BK][BN];
    __shared__ int   stok[BM];

    if (UP) {
        if (tid < BM) {
            int gr = rt * BM + tid;
            stok[tid] = g_btok[off + ((gr < cnt) ? gr : (cnt - 1))];
        }
    }
    __syncthreads();

    const float* Bexp = Bg + (size_t)e * KD * ND;

    float acc[TM][TN];
#pragma unroll
    for (int i = 0; i < TM; i++)
#pragma unroll
        for (int j = 0; j < TN; j++) acc[i][j] = 0.f;

    auto load_tile = [&](int kt, int buf) {
#pragma unroll
        for (int i = 0; i < 2; i++) {
            int slot = tid + i * 256;
            int row = slot >> 2, k4 = slot & 3;
            const float* src;
            if (UP) {
                src = Ag + (size_t)stok[row] * KD + kt + k4 * 4;
            } else {
                int gr = rt * BM + row;
                if (gr >= cnt) gr = cnt - 1;
                src = g_h + (size_t)(off + gr) * KD + kt + k4 * 4;
            }
            float4 v = *(const float4*)src;
            As[buf][k4 * 4 + 0][row] = v.x;
            As[buf][k4 * 4 + 1][row] = v.y;
            As[buf][k4 * 4 + 2][row] = v.z;
            As[buf][k4 * 4 + 3][row] = v.w;
        }
#pragma unroll
        for (int i = 0; i < 2; i++) {
            int slot = tid + i * 256;
            int kk = slot >> 5, n4 = slot & 31;
            float4 v = *(const float4*)(Bexp + (size_t)(kt + kk) * ND + n0 + n4 * 4);
            *(float4*)&Bs[buf][kk][n4 * 4] = v;
        }
    };

    load_tile(0, 0);
    __syncthreads();

    const int tx = tid & 15, ty = tid >> 4;
    const int NK = KD / BK;
    for (int kt = 0; kt < NK; kt++) {
        int cur = kt & 1;
        if (kt + 1 < NK) load_tile((kt + 1) * BK, cur ^ 1);
#pragma unroll
        for (int k = 0; k < BK; k++) {
            float a[TM], b[TN];
#pragma unroll
            for (int i = 0; i < TM; i++) a[i] = As[cur][k][ty * TM + i];
#pragma unroll
            for (int j = 0; j < TN; j++) b[j] = Bs[cur][k][tx * TN + j];
#pragma unroll
            for (int i = 0; i < TM; i++)
#pragma unroll
                for (int j = 0; j < TN; j++) acc[i][j] = fmaf(a[i], b[j], acc[i][j]);
        }
        __syncthreads();
    }

    // epilogue
#pragma unroll
    for (int i = 0; i < TM; i++) {
        int gr = rt * BM + ty * TM + i;
        if (gr >= cnt) continue;
        float* crow;
        float gate = 1.f;
        if (UP) {
            gate = g_bw[off + gr];
            crow = g_h + (size_t)(off + gr) * ND;
        } else {
            crow = g_yb + (size_t)(off + gr) * ND;
        }
#pragma unroll
        for (int j = 0; j < TN; j += 4) {
            float vv[4];
#pragma unroll
            for (int q = 0; q < 4; q++) {
                float z = acc[i][j + q];
                if (UP) {
                    // exact GELU: z * 0.5 * (1 + erf(z/sqrt(2))), then gate
                    z = 0.5f * z * (1.f + erff(z * 0.70710678118654752f)) * gate;
                }
                vv[q] = z;
            }
            float4 v = make_float4(vv[0], vv[1], vv[2], vv[3]);
            *(float4*)(crow + n0 + tx * TN + j) = v;
        }
    }
}

__global__ void k_combine(float* __restrict__ y) {
    int i = blockIdx.x * blockDim.x + threadIdx.x;
    const int nv = TT * DD / 4;
    if (i >= nv) return;
    int t = i / (DD / 4);
    int d4 = i % (DD / 4);
    int p0 = g_pos[2 * t], p1 = g_pos[2 * t + 1];
    float4 a = ((const float4*)(g_yb + (size_t)p0 * DD))[d4];
    float4 b = ((const float4*)(g_yb + (size_t)p1 * DD))[d4];
    float4 o = make_float4(a.x + b.x, a.y + b.y, a.z + b.z, a.w + b.w);
    ((float4*)(y + (size_t)t * DD))[d4] = o;
}

// ---------------- launch -----------------------------------------------------

extern "C" void kernel_launch(void* const* d_in, const int* in_sizes, int n_in,
                              void* d_out, int out_size) {
    const float* x  = (const float*)d_in[0];
    const float* Wg = (const float*)d_in[1];
    const float* W1 = (const float*)d_in[2];
    const float* W2 = (const float*)d_in[3];
    float* out = (float*)d_out;
    float* y = out;                                 // [T, D]
    float* logits = out + (size_t)TT * DD;          // [T, E]

    k_zero<<<1, 32>>>();
    k_router<<<TT / 8, 256>>>(x, Wg, logits);
    k_offsets<<<1, 1>>>();
    k_scatter<<<TT / 256, 256>>>();

    dim3 gup(HH / BN, TT / BM, EE);
    k_ggemm<DD, HH, true><<<gup, 256>>>(x, W1);

    dim3 gdn(DD / BN, TT / BM, EE);
    k_ggemm<HH, DD, false><<<gdn, 256>>>(nullptr, W2);

    k_combine<<<(TT * DD / 4 + 255) / 256, 256>>>(y);
}